// round 13
// baseline (speedup 1.0000x reference)
#include <cuda_runtime.h>
#include <math.h>
#include <stdint.h>

#define XD    50
#define LEN   230
#define KF    150
#define KSTEPS 20          // K padded to 160 = 20 x 8
#define NOUT  1380
#define NP    1408
#define BTOT  16384

typedef unsigned long long ull;

// A fragment-major: [mtile(16 rows)][kstep(8 cols)][lane*4+slot]
__device__ __align__(16) float g_flatF[(BTOT / 16) * KSTEPS * 128];
// B fragment-major: [n8tile][kstep][lane*2+slot]
__device__ __align__(16) float g_WF[(NP / 8) * KSTEPS * 64];

// ---------------- helpers ----------------
__device__ __forceinline__ ull pk(float lo, float hi) {
    ull r; asm("mov.b64 %0, {%1, %2};" : "=l"(r) : "f"(lo), "f"(hi)); return r;
}
__device__ __forceinline__ void unpk(ull v, float& lo, float& hi) {
    asm("mov.b64 {%0, %1}, %2;" : "=f"(lo), "=f"(hi) : "l"(v));
}
__device__ __forceinline__ ull fma2(ull a, ull b, ull c) {
    ull d; asm("fma.rn.f32x2 %0, %1, %2, %3;" : "=l"(d) : "l"(a), "l"(b), "l"(c)); return d;
}
__device__ __forceinline__ ull mul2(ull a, ull b) {
    ull d; asm("mul.rn.f32x2 %0, %1, %2;" : "=l"(d) : "l"(a), "l"(b)); return d;
}
__device__ __forceinline__ ull add2(ull a, ull b) {
    ull d; asm("add.rn.f32x2 %0, %1, %2;" : "=l"(d) : "l"(a), "l"(b)); return d;
}
__device__ __forceinline__ float tf32r(float x) {
    unsigned u; asm("cvt.rna.tf32.f32 %0, %1;" : "=r"(u) : "f"(x));
    return __uint_as_float(u);
}
__device__ __forceinline__ uint32_t smem_u32(const void* p) {
    uint32_t a;
    asm("{ .reg .u64 t; cvta.to.shared.u64 t, %1; cvt.u32.u64 %0, t; }" : "=r"(a) : "l"(p));
    return a;
}
__device__ __forceinline__ void cp16(uint32_t dst, const void* src) {
    asm volatile("cp.async.cg.shared.global [%0], [%1], 16;" :: "r"(dst), "l"(src) : "memory");
}

// fragment-major index for A element (b, k)
__device__ __forceinline__ int a_idx(int b, int k) {
    int mt = b >> 4, row = b & 15, ks = k >> 3, kc = k & 7;
    int lane = ((row & 7) << 2) | (kc & 3);
    int slot = ((kc >> 2) << 1) | (row >> 3);
    return (mt * KSTEPS + ks) * 128 + lane * 4 + slot;
}

// ---------------------------------------------------------------------------
// Stage 0: w_out [NOUT][KF] -> g_WF fragment-major (tf32-rounded, zero pad)
// ---------------------------------------------------------------------------
__global__ __launch_bounds__(256) void wt_kernel(const float* __restrict__ W)
{
    int i = blockIdx.x * 256 + threadIdx.x;
    if (i >= (NP / 8) * KSTEPS * 64) return;
    int n8 = i / (KSTEPS * 64);
    int r  = i - n8 * (KSTEPS * 64);
    int ks = r >> 6, q = r & 63;
    int lane = q >> 1, slot = q & 1;
    int n = n8 * 8 + (lane >> 2);
    int k = ks * 8 + (lane & 3) + 4 * slot;
    g_WF[i] = (n < NOUT && k < KF) ? tf32r(W[n * KF + k]) : 0.f;
}

// ---------------------------------------------------------------------------
// Stage 1: conv + max, ring[20] global-LDG with lead-9 schedule:
// CS(p); LS(p+9). Slot (p+9)%20 holds x[p-11], dead after CS(p).
// conv12/conv6 computed as split parallel chains joined by add.rn.f32x2.
// 128-thread CTAs, reg-capped for 5 CTA/SM (20 warps).
// ---------------------------------------------------------------------------
template<int S, bool C1, bool C2, bool C3>
__device__ __forceinline__ void comp_step(
    ull (&ring)[20],
    const ull* __restrict__ wa, const ull* __restrict__ wb, const ull* __restrict__ wc,
    float& m1a, float& m1b, float& m2a, float& m2b, float& m3a, float& m3b)
{
    float x, y;
    if (C1) {   // x[p-2..p] -> slots (S+18)%20, (S+19)%20, S
        ull s = mul2(wa[0], ring[(S + 18) % 20]);
        s = fma2(wa[1], ring[(S + 19) % 20], s);
        s = fma2(wa[2], ring[S], s);
        unpk(s, x, y); m1a = fmaxf(m1a, x); m1b = fmaxf(m1b, y);
    }
    if (C2) {   // x[p-5..p] -> slots (S+15+i)%20 ; two 3-chains + add
        ull sA = mul2(wb[0], ring[(S + 15) % 20]);
        sA = fma2(wb[1], ring[(S + 16) % 20], sA);
        sA = fma2(wb[2], ring[(S + 17) % 20], sA);
        ull sB = mul2(wb[3], ring[(S + 18) % 20]);
        sB = fma2(wb[4], ring[(S + 19) % 20], sB);
        sB = fma2(wb[5], ring[S], sB);
        ull s = add2(sA, sB);
        unpk(s, x, y); m2a = fmaxf(m2a, x); m2b = fmaxf(m2b, y);
    }
    if (C3) {   // x[p-11..p] -> slots (S+9+i)%20 ; two 6-chains + add
        ull sA = mul2(wc[0], ring[(S + 9) % 20]);
        #pragma unroll
        for (int i = 1; i < 6; i++) sA = fma2(wc[i], ring[(S + 9 + i) % 20], sA);
        ull sB = mul2(wc[6], ring[(S + 15) % 20]);
        #pragma unroll
        for (int i = 7; i < 12; i++) sB = fma2(wc[i], ring[(S + 9 + i) % 20], sB);
        ull s = add2(sA, sB);
        unpk(s, x, y); m3a = fmaxf(m3a, x); m3b = fmaxf(m3b, y);
    }
}

__global__ __launch_bounds__(128, 5) void conv_max_kernel(
    const float* __restrict__ seq,
    const float* __restrict__ w1, const float* __restrict__ b1,
    const float* __restrict__ w2, const float* __restrict__ b2,
    const float* __restrict__ w3, const float* __restrict__ b3,
    int nthreads)
{
    const int t = blockIdx.x * 128 + threadIdx.x;
    if (t >= nthreads) return;
    const int b  = t / 25;
    const int p  = t - b * 25;
    const int c0 = 2 * p, c1 = 2 * p + 1;

    const float* base = seq + (size_t)b * (LEN * XD) + c0;

    ull wa[3], wb[6], wc[12];
    #pragma unroll
    for (int i = 0; i < 3;  i++) wa[i] = pk(w1[3 * c0 + i],  w1[3 * c1 + i]);
    #pragma unroll
    for (int i = 0; i < 6;  i++) wb[i] = pk(w2[6 * c0 + i],  w2[6 * c1 + i]);
    #pragma unroll
    for (int i = 0; i < 12; i++) wc[i] = pk(w3[12 * c0 + i], w3[12 * c1 + i]);

    ull ring[20];
    float m1a = -INFINITY, m1b = -INFINITY;
    float m2a = -INFINITY, m2b = -INFINITY;
    float m3a = -INFINITY, m3b = -INFINITY;

    #define LS(S, L)  ring[S] = *(const ull*)(base + (L) * XD)
    #define CS(S, A, Bf, C) \
        comp_step<S, A, Bf, C>(ring, wa, wb, wc, m1a, m1b, m2a, m2b, m3a, m3b)

    // initial fill: positions 0..8 -> slots 0..8 (MLP=9)
    LS(0, 0);  LS(1, 1);  LS(2, 2);  LS(3, 3);  LS(4, 4);
    LS(5, 5);  LS(6, 6);  LS(7, 7);  LS(8, 8);

    // prologue p = 0..10: partial convs; each step loads p+9
    LS(9, 9);                                     // p=0
    LS(10, 10);                                   // p=1
    CS(2,  true, false, false); LS(11, 11);
    CS(3,  true, false, false); LS(12, 12);
    CS(4,  true, false, false); LS(13, 13);
    CS(5,  true, true,  false); LS(14, 14);
    CS(6,  true, true,  false); LS(15, 15);
    CS(7,  true, true,  false); LS(16, 16);
    CS(8,  true, true,  false); LS(17, 17);
    CS(9,  true, true,  false); LS(18, 18);
    CS(10, true, true,  false); LS(19, 19);

    // main: p = 11..210, 10 blocks of 20. step: CS(p); LS((p+9)%20, p+9)
    const float* bp = base + 11 * XD;   // p0 = 11 + 20*blk
    #define M(S, OFF) \
        CS(S, true, true, true); \
        ring[(S + 9) % 20] = *(const ull*)(bp + (OFF + 9) * XD)
    #pragma unroll 1
    for (int blk = 0; blk < 10; blk++, bp += 20 * XD) {
        M(11, 0); M(12, 1); M(13, 2); M(14, 3); M(15, 4);
        M(16, 5); M(17, 6); M(18, 7); M(19, 8); M(0, 9);
        M(1, 10); M(2, 11); M(3, 12); M(4, 13); M(5, 14);
        M(6, 15); M(7, 16); M(8, 17); M(9, 18); M(10, 19);
    }
    #undef M

    // tail: p = 211..220 with loads (220..229), then p = 221..229 compute-only
    CS(11, true, true, true); LS(0, 220);
    CS(12, true, true, true); LS(1, 221);
    CS(13, true, true, true); LS(2, 222);
    CS(14, true, true, true); LS(3, 223);
    CS(15, true, true, true); LS(4, 224);
    CS(16, true, true, true); LS(5, 225);
    CS(17, true, true, true); LS(6, 226);
    CS(18, true, true, true); LS(7, 227);
    CS(19, true, true, true); LS(8, 228);
    CS(0,  true, true, true); LS(9, 229);
    CS(1,  true, true, true);
    CS(2,  true, true, true);
    CS(3,  true, true, true);
    CS(4,  true, true, true);
    CS(5,  true, true, true);
    CS(6,  true, true, true);
    CS(7,  true, true, true);
    CS(8,  true, true, true);
    CS(9,  true, true, true);
    #undef LS
    #undef CS

    g_flatF[a_idx(b, 3 * c0 + 0)] = tf32r(m1a + b1[c0]);
    g_flatF[a_idx(b, 3 * c0 + 1)] = tf32r(m2a + b2[c0]);
    g_flatF[a_idx(b, 3 * c0 + 2)] = tf32r(m3a + b3[c0]);
    g_flatF[a_idx(b, 3 * c1 + 0)] = tf32r(m1b + b1[c1]);
    g_flatF[a_idx(b, 3 * c1 + 1)] = tf32r(m2b + b2[c1]);
    g_flatF[a_idx(b, 3 * c1 + 2)] = tf32r(m3b + b3[c1]);
    if (p < 5) {
        g_flatF[a_idx(b, KF + 2 * p)]     = 0.f;
        g_flatF[a_idx(b, KF + 2 * p + 1)] = 0.f;
    }
}

// ---------------------------------------------------------------------------
// Stage 2: tf32 mma.sync GEMM, cp.async double-buffered over 4 K-chunks of
// 5 ksteps. CTA 128x128, 8 warps 2x4, warp tile 64x32. 80KB smem -> 2 CTA/SM.
// ---------------------------------------------------------------------------
#define CH_A 1280
#define CH_B 1280
#define BUF_F4 (CH_A + CH_B)
#define SMEM_SZ (2 * BUF_F4 * 16)   // 80KB

__device__ __forceinline__ void mma_tf32_16n8k8(
    float& c0, float& c1, float& c2, float& c3,
    uint32_t a0, uint32_t a1, uint32_t a2, uint32_t a3,
    uint32_t b0, uint32_t b1)
{
    asm volatile(
        "mma.sync.aligned.m16n8k8.row.col.f32.tf32.tf32.f32 "
        "{%0,%1,%2,%3}, {%4,%5,%6,%7}, {%8,%9}, {%0,%1,%2,%3};"
        : "+f"(c0), "+f"(c1), "+f"(c2), "+f"(c3)
        : "r"(a0), "r"(a1), "r"(a2), "r"(a3), "r"(b0), "r"(b1));
}

__global__ __launch_bounds__(256, 2)
void mma_kernel(const float* __restrict__ bias, float* __restrict__ out, int nbat)
{
    extern __shared__ float smem[];
    const uint32_t sb = smem_u32(smem);
    const int tid  = threadIdx.x;
    const int warp = tid >> 5, lane = tid & 31;
    const int wm = warp & 1, wn = warp >> 1;
    const int bm = blockIdx.y * 128, bn = blockIdx.x * 128;
    const int mtg = bm >> 4, ntg = bn >> 3;

    const float4* gA = (const float4*)g_flatF;
    const float4* gB = (const float4*)g_WF;

    auto prefetch = [&](int c, int buf) {
        uint32_t dbase = sb + buf * (BUF_F4 * 16);
        #pragma unroll
        for (int rep = 0; rep < 10; rep++) {
            int i = tid + rep * 256;
            if (i < CH_A) {
                int mt = i / 160, r = i - mt * 160;
                cp16(dbase + i * 16, gA + (size_t)((mtg + mt) * KSTEPS + c * 5) * 32 + r);
            } else {
                int j = i - CH_A;
                int nt = j / 80, r = j - nt * 80;
                cp16(dbase + i * 16, gB + (size_t)((ntg + nt) * KSTEPS + c * 5) * 16 + r);
            }
        }
        asm volatile("cp.async.commit_group;" ::: "memory");
    };

    float acc[4][4][4];
    #pragma unroll
    for (int i = 0; i < 4; i++)
        #pragma unroll
        for (int j = 0; j < 4; j++)
            #pragma unroll
            for (int r = 0; r < 4; r++) acc[i][j][r] = 0.f;

    prefetch(0, 0);
    #pragma unroll
    for (int c = 0; c < 4; c++) {
        if (c < 3) prefetch(c + 1, (c + 1) & 1);
        if (c < 3) asm volatile("cp.async.wait_group 1;" ::: "memory");
        else       asm volatile("cp.async.wait_group 0;" ::: "memory");
        __syncthreads();

        const float* buf = smem + (c & 1) * (BUF_F4 * 4);
        const float* sA = buf;
        const float* sB = buf + CH_A * 4;
        #pragma unroll
        for (int ks = 0; ks < 5; ks++) {
            uint32_t a[4][4], b[4][2];
            #pragma unroll
            for (int mt = 0; mt < 4; mt++) {
                float4 v = *(const float4*)(sA + ((wm * 4 + mt) * 5 + ks) * 128 + lane * 4);
                a[mt][0] = __float_as_uint(v.x); a[mt][1] = __float_as_uint(v.y);
                a[mt][2] = __float_as_uint(v.z); a[mt][3] = __float_as_uint(v.w);
            }
            #pragma unroll
            for (int nt = 0; nt < 4; nt++) {
                float2 v = *(const float2*)(sB + ((wn * 4 + nt) * 5 + ks) * 64 + lane * 2);
                b[nt][0] = __float_as_uint(v.x); b[nt][1] = __float_as_uint(v.y);
            }
            #pragma unroll
            for (int mt = 0; mt < 4; mt++)
                #pragma unroll
                for (int nt = 0; nt < 4; nt++)
                    mma_tf32_16n8k8(acc[mt][nt][0], acc[mt][nt][1],
                                    acc[mt][nt][2], acc[mt][nt][3],
                                    a[mt][0], a[mt][1], a[mt][2], a[mt][3],
                                    b[nt][0], b[nt][1]);
        }
        __syncthreads();
    }

    const int g  = lane >> 2;
    const int tg = lane & 3;
    #pragma unroll
    for (int mt = 0; mt < 4; mt++) {
        int row0 = bm + wm * 64 + mt * 16 + g;
        int row1 = row0 + 8;
        #pragma unroll
        for (int nt = 0; nt < 4; nt++) {
            int col = bn + wn * 32 + nt * 8 + 2 * tg;
            if (col < NOUT) {
                float2 bb = *(const float2*)(bias + col);
                if (row0 < nbat) {
                    float2 v = {acc[mt][nt][0] + bb.x, acc[mt][nt][1] + bb.y};
                    *(float2*)(out + (size_t)row0 * NOUT + col) = v;
                }
                if (row1 < nbat) {
                    float2 v = {acc[mt][nt][2] + bb.x, acc[mt][nt][3] + bb.y};
                    *(float2*)(out + (size_t)row1 * NOUT + col) = v;
                }
            }
        }
    }
}

// ---------------------------------------------------------------------------
extern "C" void kernel_launch(void* const* d_in, const int* in_sizes, int n_in,
                              void* d_out, int out_size)
{
    const float* seq   = (const float*)d_in[0];
    const float* w1    = (const float*)d_in[1];
    const float* b1    = (const float*)d_in[2];
    const float* w2    = (const float*)d_in[3];
    const float* b2    = (const float*)d_in[4];
    const float* w3    = (const float*)d_in[5];
    const float* b3    = (const float*)d_in[6];
    const float* w_out = (const float*)d_in[7];
    const float* b_out = (const float*)d_in[8];
    float* out = (float*)d_out;

    const int B = in_sizes[0] / (LEN * XD);
    const int nthreads = B * 25;

    static int smem_set = 0;
    if (!smem_set) {
        cudaFuncSetAttribute(mma_kernel, cudaFuncAttributeMaxDynamicSharedMemorySize, SMEM_SZ);
        smem_set = 1;
    }

    conv_max_kernel<<<(nthreads + 127) / 128, 128>>>(seq, w1, b1, w2, b2, w3, b3, nthreads);
    wt_kernel<<<((NP / 8) * KSTEPS * 64 + 255) / 256, 256>>>(w_out);

    dim3 grid(NP / 128, (B + 127) / 128);
    mma_kernel<<<grid, 256, SMEM_SZ>>>(b_out, out, B);
}

// round 14
// speedup vs baseline: 1.5116x; 1.5116x over previous
#include <cuda_runtime.h>
#include <cuda_fp16.h>
#include <math.h>
#include <stdint.h>

#define XD    50
#define LEN   230
#define KF    150
#define KS2   10           // K padded to 160 = 10 x 16
#define NOUT  1380
#define NP    1408
#define BTOT  16384

typedef unsigned long long ull;

// A fragment-major fp16: [mtile][kstep16][lane*8 + reg*2 + h]
__device__ __align__(16) __half g_flatH[(BTOT / 16) * KS2 * 256];
// B fragment-major fp16: [n8tile][kstep16][lane*4 + reg*2 + h]
__device__ __align__(16) __half g_WH[(NP / 8) * KS2 * 128];

// ---------------- helpers ----------------
__device__ __forceinline__ ull pk(float lo, float hi) {
    ull r; asm("mov.b64 %0, {%1, %2};" : "=l"(r) : "f"(lo), "f"(hi)); return r;
}
__device__ __forceinline__ void unpk(ull v, float& lo, float& hi) {
    asm("mov.b64 {%0, %1}, %2;" : "=f"(lo), "=f"(hi) : "l"(v));
}
__device__ __forceinline__ ull fma2(ull a, ull b, ull c) {
    ull d; asm("fma.rn.f32x2 %0, %1, %2, %3;" : "=l"(d) : "l"(a), "l"(b), "l"(c)); return d;
}
__device__ __forceinline__ ull mul2(ull a, ull b) {
    ull d; asm("mul.rn.f32x2 %0, %1, %2;" : "=l"(d) : "l"(a), "l"(b)); return d;
}
__device__ __forceinline__ uint32_t smem_u32(const void* p) {
    uint32_t a;
    asm("{ .reg .u64 t; cvta.to.shared.u64 t, %1; cvt.u32.u64 %0, t; }" : "=r"(a) : "l"(p));
    return a;
}
__device__ __forceinline__ void cp16(uint32_t dst, const void* src) {
    asm volatile("cp.async.cg.shared.global [%0], [%1], 16;" :: "r"(dst), "l"(src) : "memory");
}

// fp16 fragment-major index for A element (b=row in M, k)
__device__ __forceinline__ int ah_idx(int b, int k) {
    int mt = b >> 4, row = b & 15, ks = k >> 4, kc = k & 15;
    int lane = ((row & 7) << 2) | ((kc >> 1) & 3);
    int reg  = ((kc >> 3) << 1) | (row >> 3);
    return ((mt * KS2 + ks) * 32 + lane) * 8 + reg * 2 + (kc & 1);
}

// ---------------------------------------------------------------------------
// Stage 0: w_out [NOUT][KF] -> g_WH fragment-major (fp16, zero pad)
// ---------------------------------------------------------------------------
__global__ __launch_bounds__(256) void wt_kernel(const float* __restrict__ W)
{
    int i = blockIdx.x * 256 + threadIdx.x;
    if (i >= (NP / 8) * KS2 * 128) return;
    int n8 = i / (KS2 * 128);
    int r  = i - n8 * (KS2 * 128);
    int ks = r >> 7, q = r & 127;
    int lane = q >> 2, reg = (q >> 1) & 1, h = q & 1;
    int n  = n8 * 8 + (lane >> 2);
    int kc = ((lane & 3) << 1) | h | (reg << 3);
    int k  = ks * 16 + kc;
    g_WH[i] = (n < NOUT && k < KF) ? __float2half_rn(W[n * KF + k]) : __float2half_rn(0.f);
}

// ---------------------------------------------------------------------------
// Stage 1: conv + max, ring[24] global-LDG, lead-13 schedule (exact R7 code;
// proven 171us). Epilogue writes fp16 fragments.
// ---------------------------------------------------------------------------
template<int S, bool C1, bool C2, bool C3>
__device__ __forceinline__ void comp_step(
    ull (&ring)[24],
    const ull* __restrict__ wa, const ull* __restrict__ wb, const ull* __restrict__ wc,
    float& m1a, float& m1b, float& m2a, float& m2b, float& m3a, float& m3b)
{
    float x, y;
    if (C1) {
        ull s = mul2(wa[0], ring[(S + 22) % 24]);
        s = fma2(wa[1], ring[(S + 23) % 24], s);
        s = fma2(wa[2], ring[S], s);
        unpk(s, x, y); m1a = fmaxf(m1a, x); m1b = fmaxf(m1b, y);
    }
    if (C2) {
        ull s = mul2(wb[0], ring[(S + 19) % 24]);
        #pragma unroll
        for (int i = 1; i < 6; i++) s = fma2(wb[i], ring[(S + 19 + i) % 24], s);
        unpk(s, x, y); m2a = fmaxf(m2a, x); m2b = fmaxf(m2b, y);
    }
    if (C3) {
        ull s = mul2(wc[0], ring[(S + 13) % 24]);
        #pragma unroll
        for (int i = 1; i < 12; i++) s = fma2(wc[i], ring[(S + 13 + i) % 24], s);
        unpk(s, x, y); m3a = fmaxf(m3a, x); m3b = fmaxf(m3b, y);
    }
}

__global__ __launch_bounds__(256) void conv_max_kernel(
    const float* __restrict__ seq,
    const float* __restrict__ w1, const float* __restrict__ b1,
    const float* __restrict__ w2, const float* __restrict__ b2,
    const float* __restrict__ w3, const float* __restrict__ b3,
    int nthreads)
{
    const int t = blockIdx.x * 256 + threadIdx.x;
    if (t >= nthreads) return;
    const int b  = t / 25;
    const int p  = t - b * 25;
    const int c0 = 2 * p, c1 = 2 * p + 1;

    const float* base = seq + (size_t)b * (LEN * XD) + c0;

    ull wa[3], wb[6], wc[12];
    #pragma unroll
    for (int i = 0; i < 3;  i++) wa[i] = pk(w1[3 * c0 + i],  w1[3 * c1 + i]);
    #pragma unroll
    for (int i = 0; i < 6;  i++) wb[i] = pk(w2[6 * c0 + i],  w2[6 * c1 + i]);
    #pragma unroll
    for (int i = 0; i < 12; i++) wc[i] = pk(w3[12 * c0 + i], w3[12 * c1 + i]);

    ull ring[24];
    float m1a = -INFINITY, m1b = -INFINITY;
    float m2a = -INFINITY, m2b = -INFINITY;
    float m3a = -INFINITY, m3b = -INFINITY;

    #define LS(S, L)  ring[S] = *(const ull*)(base + (L) * XD)
    #define CS(S, A, Bf, C) \
        comp_step<S, A, Bf, C>(ring, wa, wb, wc, m1a, m1b, m2a, m2b, m3a, m3b)

    LS(0, 0);  LS(1, 1);  LS(2, 2);  LS(3, 3);  LS(4, 4);  LS(5, 5);  LS(6, 6);
    LS(7, 7);  LS(8, 8);  LS(9, 9);  LS(10, 10); LS(11, 11); LS(12, 12);

    LS(13, 13);
    LS(14, 14);
    CS(2,  true, false, false); LS(15, 15);
    CS(3,  true, false, false); LS(16, 16);
    CS(4,  true, false, false); LS(17, 17);
    CS(5,  true, true,  false); LS(18, 18);
    CS(6,  true, true,  false); LS(19, 19);
    CS(7,  true, true,  false); LS(20, 20);
    CS(8,  true, true,  false); LS(21, 21);
    CS(9,  true, true,  false); LS(22, 22);
    CS(10, true, true,  false); LS(23, 23);

    const float* bp = base + 11 * XD;
    #define M(S, OFF) \
        CS(S, true, true, true); \
        ring[(S + 13) % 24] = *(const ull*)(bp + (OFF + 13) * XD)
    #pragma unroll 1
    for (int blk = 0; blk < 8; blk++, bp += 24 * XD) {
        M(11, 0);  M(12, 1);  M(13, 2);  M(14, 3);  M(15, 4);  M(16, 5);
        M(17, 6);  M(18, 7);  M(19, 8);  M(20, 9);  M(21, 10); M(22, 11);
        M(23, 12); M(0, 13);  M(1, 14);  M(2, 15);  M(3, 16);  M(4, 17);
        M(5, 18);  M(6, 19);  M(7, 20);  M(8, 21);  M(9, 22);  M(10, 23);
    }
    #undef M

    CS(11, true, true, true); LS(0, 216);
    CS(12, true, true, true); LS(1, 217);
    CS(13, true, true, true); LS(2, 218);
    CS(14, true, true, true); LS(3, 219);
    CS(15, true, true, true); LS(4, 220);
    CS(16, true, true, true); LS(5, 221);
    CS(17, true, true, true); LS(6, 222);
    CS(18, true, true, true); LS(7, 223);
    CS(19, true, true, true); LS(8, 224);
    CS(20, true, true, true); LS(9, 225);
    CS(21, true, true, true); LS(10, 226);
    CS(22, true, true, true); LS(11, 227);
    CS(23, true, true, true); LS(12, 228);
    CS(0,  true, true, true); LS(13, 229);
    CS(1,  true, true, true);
    CS(2,  true, true, true);
    CS(3,  true, true, true);
    CS(4,  true, true, true);
    CS(5,  true, true, true);
    CS(6,  true, true, true);
    CS(7,  true, true, true);
    CS(8,  true, true, true);
    CS(9,  true, true, true);
    CS(10, true, true, true);
    CS(11, true, true, true);
    CS(12, true, true, true);
    CS(13, true, true, true);
    #undef LS
    #undef CS

    g_flatH[ah_idx(b, 3 * c0 + 0)] = __float2half_rn(m1a + b1[c0]);
    g_flatH[ah_idx(b, 3 * c0 + 1)] = __float2half_rn(m2a + b2[c0]);
    g_flatH[ah_idx(b, 3 * c0 + 2)] = __float2half_rn(m3a + b3[c0]);
    g_flatH[ah_idx(b, 3 * c1 + 0)] = __float2half_rn(m1b + b1[c1]);
    g_flatH[ah_idx(b, 3 * c1 + 1)] = __float2half_rn(m2b + b2[c1]);
    g_flatH[ah_idx(b, 3 * c1 + 2)] = __float2half_rn(m3b + b3[c1]);
    if (p < 5) {
        g_flatH[ah_idx(b, KF + 2 * p)]     = __float2half_rn(0.f);
        g_flatH[ah_idx(b, KF + 2 * p + 1)] = __float2half_rn(0.f);
    }
}

// ---------------------------------------------------------------------------
// Stage 2: fp16 mma.sync m16n8k16 GEMM, cp.async double-buffered over 2
// K-chunks of 5 ksteps (K=80 each). CTA 128x128, 8 warps 2x4, warp 64x32.
// ---------------------------------------------------------------------------
#define CH_A 1280            // float4 per chunk (A): 8mt*5ks*512B/16
#define CH_B 1280            // float4 per chunk (B): 16nt*5ks*256B/16
#define BUF_F4 (CH_A + CH_B) // 40KB
#define SMEM_SZ (2 * BUF_F4 * 16)   // 80KB

__device__ __forceinline__ void mma_f16_16n8k16(
    float& c0, float& c1, float& c2, float& c3,
    uint32_t a0, uint32_t a1, uint32_t a2, uint32_t a3,
    uint32_t b0, uint32_t b1)
{
    asm volatile(
        "mma.sync.aligned.m16n8k16.row.col.f32.f16.f16.f32 "
        "{%0,%1,%2,%3}, {%4,%5,%6,%7}, {%8,%9}, {%0,%1,%2,%3};"
        : "+f"(c0), "+f"(c1), "+f"(c2), "+f"(c3)
        : "r"(a0), "r"(a1), "r"(a2), "r"(a3), "r"(b0), "r"(b1));
}

__global__ __launch_bounds__(256, 2)
void mma_kernel(const float* __restrict__ bias, float* __restrict__ out, int nbat)
{
    extern __shared__ char smem[];
    const uint32_t sb = smem_u32(smem);
    const int tid  = threadIdx.x;
    const int warp = tid >> 5, lane = tid & 31;
    const int wm = warp & 1, wn = warp >> 1;
    const int bm = blockIdx.y * 128, bn = blockIdx.x * 128;
    const int mtg = bm >> 4, ntg = bn >> 3;

    const float4* gA = (const float4*)g_flatH;
    const float4* gB = (const float4*)g_WH;

    auto prefetch = [&](int c, int buf) {
        uint32_t dbase = sb + buf * (BUF_F4 * 16);
        #pragma unroll
        for (int rep = 0; rep < 10; rep++) {
            int i = tid + rep * 256;
            if (i < CH_A) {
                int mt = i / 160, r = i - mt * 160;
                cp16(dbase + i * 16, gA + (size_t)((mtg + mt) * KS2 + c * 5) * 32 + r);
            } else {
                int j = i - CH_A;
                int nt = j / 80, r = j - nt * 80;
                cp16(dbase + i * 16, gB + (size_t)((ntg + nt) * KS2 + c * 5) * 16 + r);
            }
        }
        asm volatile("cp.async.commit_group;" ::: "memory");
    };

    float acc[4][4][4];
    #pragma unroll
    for (int i = 0; i < 4; i++)
        #pragma unroll
        for (int j = 0; j < 4; j++)
            #pragma unroll
            for (int r = 0; r < 4; r++) acc[i][j][r] = 0.f;

    prefetch(0, 0);
    #pragma unroll
    for (int c = 0; c < 2; c++) {
        if (c < 1) { prefetch(1, 1); asm volatile("cp.async.wait_group 1;" ::: "memory"); }
        else       { asm volatile("cp.async.wait_group 0;" ::: "memory"); }
        __syncthreads();

        const char* buf = smem + (c & 1) * (BUF_F4 * 16);
        const char* sA = buf;
        const char* sB = buf + CH_A * 16;
        #pragma unroll
        for (int ks = 0; ks < 5; ks++) {
            uint32_t a[4][4], b[4][2];
            #pragma unroll
            for (int mt = 0; mt < 4; mt++) {
                uint4 v = *(const uint4*)(sA + ((wm * 4 + mt) * 5 + ks) * 512 + lane * 16);
                a[mt][0] = v.x; a[mt][1] = v.y; a[mt][2] = v.z; a[mt][3] = v.w;
            }
            #pragma unroll
            for (int nt = 0; nt < 4; nt++) {
                uint2 v = *(const uint2*)(sB + ((wn * 4 + nt) * 5 + ks) * 256 + lane * 8);
                b[nt][0] = v.x; b[nt][1] = v.y;
            }
            #pragma unroll
            for (int mt = 0; mt < 4; mt++)
                #pragma unroll
                for (int nt = 0; nt < 4; nt++)
                    mma_f16_16n8k16(acc[mt][nt][0], acc[mt][nt][1],
                                    acc[mt][nt][2], acc[mt][nt][3],
                                    a[mt][0], a[mt][1], a[mt][2], a[mt][3],
                                    b[nt][0], b[nt][1]);
        }
        __syncthreads();
    }

    const int g  = lane >> 2;
    const int tg = lane & 3;
    #pragma unroll
    for (int mt = 0; mt < 4; mt++) {
        int row0 = bm + wm * 64 + mt * 16 + g;
        int row1 = row0 + 8;
        #pragma unroll
        for (int nt = 0; nt < 4; nt++) {
            int col = bn + wn * 32 + nt * 8 + 2 * tg;
            if (col < NOUT) {
                float2 bb = *(const float2*)(bias + col);
                if (row0 < nbat) {
                    float2 v = {acc[mt][nt][0] + bb.x, acc[mt][nt][1] + bb.y};
                    *(float2*)(out + (size_t)row0 * NOUT + col) = v;
                }
                if (row1 < nbat) {
                    float2 v = {acc[mt][nt][2] + bb.x, acc[mt][nt][3] + bb.y};
                    *(float2*)(out + (size_t)row1 * NOUT + col) = v;
                }
            }
        }
    }
}

// ---------------------------------------------------------------------------
extern "C" void kernel_launch(void* const* d_in, const int* in_sizes, int n_in,
                              void* d_out, int out_size)
{
    const float* seq   = (const float*)d_in[0];
    const float* w1    = (const float*)d_in[1];
    const float* b1    = (const float*)d_in[2];
    const float* w2    = (const float*)d_in[3];
    const float* b2    = (const float*)d_in[4];
    const float* w3    = (const float*)d_in[5];
    const float* b3    = (const float*)d_in[6];
    const float* w_out = (const float*)d_in[7];
    const float* b_out = (const float*)d_in[8];
    float* out = (float*)d_out;

    const int B = in_sizes[0] / (LEN * XD);
    const int nthreads = B * 25;

    static int smem_set = 0;
    if (!smem_set) {
        cudaFuncSetAttribute(mma_kernel, cudaFuncAttributeMaxDynamicSharedMemorySize, SMEM_SZ);
        smem_set = 1;
    }

    conv_max_kernel<<<(nthreads + 255) / 256, 256>>>(seq, w1, b1, w2, b2, w3, b3, nthreads);
    wt_kernel<<<((NP / 8) * KS2 * 128 + 255) / 256, 256>>>(w_out);

    dim3 grid(NP / 128, (B + 127) / 128);
    mma_kernel<<<grid, 256, SMEM_SZ>>>(b_out, out, B);
}